// round 15
// baseline (speedup 1.0000x reference)
#include <cuda_runtime.h>
#include <cuda_bf16.h>
#include <cstdint>
#include <math.h>

// Problem constants: B=4, N=1024, D=128, H=64
#define BATCH 4
#define NSEQ  1024
#define DDIM  128
#define HDIM  64
#define BN    (BATCH * NSEQ)   // 4096

typedef unsigned long long ull;

// Projections stored [row][h] row-major: cp.async 16B chunks fill smem directly.
__device__ float g_pre[BN * HDIM];   // emb @ Wa + b1
__device__ float g_hj [BN * HDIM];   // emb @ Wb

// ---------------------------------------------------------------------------
// Packed f32x2 helpers
// ---------------------------------------------------------------------------
__device__ __forceinline__ void fma2u(ull& d, ull a, ull b) {
    asm("fma.rn.f32x2 %0, %1, %2, %0;" : "+l"(d) : "l"(a), "l"(b));
}
// acc += relu(a + b) * w   (measured-best inner form, R7)
__device__ __forceinline__ void rfma(ull& acc, ull a, ull b, ull w) {
    asm("{\n\t.reg .f32 lo, hi;\n\t.reg .b64 s;\n\t"
        "add.rn.f32x2 s, %1, %2;\n\t"
        "mov.b64 {lo, hi}, s;\n\t"
        "max.f32 lo, lo, 0f00000000;\n\t"
        "max.f32 hi, hi, 0f00000000;\n\t"
        "mov.b64 s, {lo, hi};\n\t"
        "fma.rn.f32x2 %0, s, %3, %0;\n\t}"
        : "+l"(acc) : "l"(a), "l"(b), "l"(w));
}
__device__ __forceinline__ float lo32(ull a) {
    return __uint_as_float((unsigned int)(a & 0xffffffffull));
}
__device__ __forceinline__ float hi32(ull a) {
    return __uint_as_float((unsigned int)(a >> 32));
}
__device__ __forceinline__ float tanh_approx(float x) {
    float y;
    asm("tanh.approx.f32 %0, %1;" : "=f"(y) : "f"(x));
    return y;
}
__device__ __forceinline__ void cp16(unsigned int dst, const float* src) {
    asm volatile("cp.async.ca.shared.global [%0], [%1], 16;"
                 :: "r"(dst), "l"(src));
}

// ---------------------------------------------------------------------------
// Kernel A: projections (R6 version: 64-row tiles, grid (64,2)) — measured best.
// dyn smem = 2 * 64*130 * 4 = 66560 B
// ---------------------------------------------------------------------------
__global__ __launch_bounds__(256) void precompute_kernel(
    const float* __restrict__ emb, const float* __restrict__ W1,
    const float* __restrict__ b1)
{
    extern __shared__ float sh[];
    float* w1t = sh;              // 64 cols * 130
    float* es  = sh + 64 * 130;   // 64 rows * 130
    const int t = threadIdx.x;
    const int row0 = blockIdx.x * 64;
    const int half = blockIdx.y;  // 0 = Wa, 1 = Wb

    for (int idx = t; idx < 64 * 128; idx += 256) {
        int c = idx & 63, d = idx >> 6;
        w1t[c * 130 + d] = W1[(half * 128 + d) * 64 + c];
    }
    for (int idx = t; idx < 64 * 128; idx += 256) {
        int d = idx & 127, r = idx >> 7;
        es[r * 130 + d] = emb[(row0 + r) * 128 + d];
    }
    __syncthreads();

    const int lane = t & 31;
    const int w    = t >> 5;
    const int c0   = w * 8;

    ull acc[2][8];
    #pragma unroll
    for (int rr = 0; rr < 2; rr++)
        #pragma unroll
        for (int cc = 0; cc < 8; cc++)
            acc[rr][cc] = 0ull;

    const float* e0p = es + lane * 130;
    const float* e1p = es + (lane + 32) * 130;

    #pragma unroll 4
    for (int d = 0; d < 128; d += 2) {
        ull e0 = *(const ull*)(e0p + d);
        ull e1 = *(const ull*)(e1p + d);
        #pragma unroll
        for (int cc = 0; cc < 8; cc++) {
            ull wv = *(const ull*)(w1t + (c0 + cc) * 130 + d);
            fma2u(acc[0][cc], e0, wv);
            fma2u(acc[1][cc], e1, wv);
        }
    }

    float* dst = half ? g_hj : g_pre;
    #pragma unroll
    for (int rr = 0; rr < 2; rr++) {
        int rowg = row0 + lane + 32 * rr;
        float s[8];
        #pragma unroll
        for (int cc = 0; cc < 8; cc++) {
            s[cc] = lo32(acc[rr][cc]) + hi32(acc[rr][cc]);
            if (half == 0) s[cc] += b1[c0 + cc];
        }
        *(float4*)(dst + rowg * 64 + c0)     = make_float4(s[0], s[1], s[2], s[3]);
        *(float4*)(dst + rowg * 64 + c0 + 4) = make_float4(s[4], s[5], s[6], s[7]);
    }
}

// ---------------------------------------------------------------------------
// Kernel B: fused pairwise core + tanh + symmetrize + negate.
// DIRECTION-SPLIT: 512-thread blocks; warps 0-7 compute s1 = preI_i + hjJ_j,
// warps 8-15 compute s2 = preJ_j + hjI_i. Each thread owns 16 accs (32 regs)
// instead of 32 (64 regs) -> ~50 regs of scheduling headroom for LDS hoisting.
// tanh results exchanged through two canonical [i][j] smem buffers; both
// mirrored gmem writes are coalesced.
// Grid (136, 2): x = unordered tile pair (I <= J), y in {0,1}; each block
// does batches y and y+2; next-batch tile fill overlaps the epilogue.
// dyn smem = (4*64*68 + 2*64*65 + 64) * 4 = 103168 B -> 1 CTA/SM (16 warps)
// ---------------------------------------------------------------------------
#define TSTRIDE 68
#define ARRW    (64 * TSTRIDE)       // 4352 words per array

__global__ __launch_bounds__(512, 1) void pair_sym_kernel(
    const float* __restrict__ W2, const float* __restrict__ b2,
    float* __restrict__ out)
{
    extern __shared__ float shB[];
    float* ts1 = shB + 4 * ARRW;          // 64*65: tanh(s1) canonical [i][j]
    float* ts2 = ts1 + 64 * 65;           // 64*65: tanh(s2) canonical [i][j]
    float* w2s = ts2 + 64 * 65;           // 64

    const int t = threadIdx.x;

    // Decode unordered pair (I, J), I <= J
    int p = blockIdx.x;
    int I = 0;
    while (p >= 16 - I) { p -= 16 - I; I++; }
    const int J = I + p;

    // Fill: 128-thread group per array, 8 x 16B cp.async per thread.
    const int arr = t >> 7;          // 0..3
    const int sub = t & 127;
    const unsigned int sbase = (unsigned int)__cvta_generic_to_shared(shB);
    const unsigned int dbase = sbase + (unsigned int)(arr * ARRW) * 4u;

    auto fill_batch = [&](int b) {
        const int baseI = b * NSEQ + I * 64;
        const int baseJ = b * NSEQ + J * 64;
        const float* srcb =
            (arr == 0) ? g_pre + baseI * 64 :
            (arr == 1) ? g_hj  + baseI * 64 :
            (arr == 2) ? g_pre + baseJ * 64 :
                         g_hj  + baseJ * 64;
        #pragma unroll
        for (int e = 0; e < 8; e++) {
            int idx = sub + 128 * e;         // 0..1023
            int row = idx >> 4;
            int q   = (idx & 15) * 4;
            cp16(dbase + (unsigned int)(row * TSTRIDE + q) * 4u,
                 srcb + row * 64 + q);
        }
        asm volatile("cp.async.commit_group;");
    };

    fill_batch(blockIdx.y);
    if (t < 64) w2s[t] = W2[t];

    // Direction split
    const int dir = t >> 8;          // 0: (I->J), 1: (J->I)
    const int tt  = t & 255;
    const int tx  = tt & 15;         // col sub-index within direction
    const int ty  = tt >> 4;         // row sub-index within direction

    // dir0: rows from preI (arr0), cols from hjJ (arr3)
    // dir1: rows from preJ (arr2), cols from hjI (arr1)
    const float* rowp = shB + (dir ? 2 * ARRW : 0)        + ty * TSTRIDE;
    const float* colp = shB + (dir ? 1 * ARRW : 3 * ARRW) + tx * TSTRIDE;

    const float b2v = b2[0];

    for (int bb = 0; bb < 2; bb++) {
        const int b = blockIdx.y + 2 * bb;

        ull acc[4][4];
        #pragma unroll
        for (int r = 0; r < 4; r++)
            #pragma unroll
            for (int c = 0; c < 4; c++) acc[r][c] = 0ull;

        asm volatile("cp.async.wait_group 0;");
        __syncthreads();

        #pragma unroll 2
        for (int hh = 0; hh < HDIM; hh += 4) {
            ulonglong2 wv = *(const ulonglong2*)(w2s + hh);
            ulonglong2 aR[4];
            #pragma unroll
            for (int r = 0; r < 4; r++)
                aR[r] = *(const ulonglong2*)(rowp + (16 * r) * TSTRIDE + hh);
            #pragma unroll
            for (int c = 0; c < 4; c++) {
                ulonglong2 bC = *(const ulonglong2*)(colp + (16 * c) * TSTRIDE + hh);
                #pragma unroll
                for (int r = 0; r < 4; r++) {
                    rfma(acc[r][c], aR[r].x, bC.x, wv.x);
                    rfma(acc[r][c], aR[r].y, bC.y, wv.y);
                }
            }
        }

        __syncthreads();                 // all warps done reading tiles
        if (bb == 0) fill_batch(blockIdx.y + 2);   // refill overlaps epilogue

        // Phase 1: own tanh values -> canonical [i][j] smem buffer
        float v[4][4];
        #pragma unroll
        for (int r = 0; r < 4; r++) {
            #pragma unroll
            for (int c = 0; c < 4; c++) {
                float s = lo32(acc[r][c]) + hi32(acc[r][c]) + b2v;
                float tv = tanh_approx(s);
                v[r][c] = tv;
                if (dir == 0)   // s1[i][j], i = ty+16r, j = tx+16c
                    ts1[(ty + 16 * r) * 65 + (tx + 16 * c)] = tv;
                else            // s2[j][i], j = ty+16r, i = tx+16c -> [i][j]
                    ts2[(tx + 16 * c) * 65 + (ty + 16 * r)] = tv;
            }
        }
        __syncthreads();

        // Phase 2: combine + coalesced stores (each dir writes its mirror)
        float* outB = out + (size_t)b * NSEQ * NSEQ;
        if (dir == 0) {
            #pragma unroll
            for (int r = 0; r < 4; r++) {
                int i = ty + 16 * r;
                #pragma unroll
                for (int c = 0; c < 4; c++) {
                    int j = tx + 16 * c;
                    float vv = -0.5f * (v[r][c] + ts2[i * 65 + j]);
                    outB[(I * 64 + i) * NSEQ + (J * 64 + j)] = vv;
                }
            }
        } else {
            #pragma unroll
            for (int r = 0; r < 4; r++) {
                int j = ty + 16 * r;
                #pragma unroll
                for (int c = 0; c < 4; c++) {
                    int i = tx + 16 * c;
                    float vv = -0.5f * (ts1[i * 65 + j] + v[r][c]);
                    outB[(J * 64 + j) * NSEQ + (I * 64 + i)] = vv;
                }
            }
        }
        __syncthreads();   // ts buffers stable before next batch reuses them
    }
}

// ---------------------------------------------------------------------------
extern "C" void kernel_launch(void* const* d_in, const int* in_sizes, int n_in,
                              void* d_out, int out_size)
{
    const float* emb = (const float*)d_in[0];
    const float* W1  = (const float*)d_in[1];
    const float* b1  = (const float*)d_in[2];
    const float* W2  = (const float*)d_in[3];
    const float* b2  = (const float*)d_in[4];
    float* out = (float*)d_out;

    const int smemA = 2 * 64 * 130 * 4;                         // 66560
    const int smemB = (4 * ARRW + 2 * 64 * 65 + 64) * 4;        // 103168

    cudaFuncSetAttribute(precompute_kernel,
                         cudaFuncAttributeMaxDynamicSharedMemorySize, smemA);
    cudaFuncSetAttribute(pair_sym_kernel,
                         cudaFuncAttributeMaxDynamicSharedMemorySize, smemB);

    precompute_kernel<<<dim3(64, 2), 256, smemA>>>(emb, W1, b1);
    pair_sym_kernel<<<dim3(136, 2), 512, smemB>>>(W2, b2, out);
}

// round 16
// speedup vs baseline: 1.0632x; 1.0632x over previous
#include <cuda_runtime.h>
#include <cuda_bf16.h>
#include <cstdint>
#include <math.h>

// Problem constants: B=4, N=1024, D=128, H=64
#define BATCH 4
#define NSEQ  1024
#define DDIM  128
#define HDIM  64
#define BN    (BATCH * NSEQ)   // 4096

typedef unsigned long long ull;

// Projections stored [row][h] row-major: cp.async 16B chunks fill smem directly.
__device__ float g_pre[BN * HDIM];   // emb @ Wa + b1
__device__ float g_hj [BN * HDIM];   // emb @ Wb

// ---------------------------------------------------------------------------
// Packed f32x2 helpers
// ---------------------------------------------------------------------------
__device__ __forceinline__ void fma2u(ull& d, ull a, ull b) {
    asm("fma.rn.f32x2 %0, %1, %2, %0;" : "+l"(d) : "l"(a), "l"(b));
}
// acc += relu(a + b) * w   (measured-best inner form, R7)
__device__ __forceinline__ void rfma(ull& acc, ull a, ull b, ull w) {
    asm("{\n\t.reg .f32 lo, hi;\n\t.reg .b64 s;\n\t"
        "add.rn.f32x2 s, %1, %2;\n\t"
        "mov.b64 {lo, hi}, s;\n\t"
        "max.f32 lo, lo, 0f00000000;\n\t"
        "max.f32 hi, hi, 0f00000000;\n\t"
        "mov.b64 s, {lo, hi};\n\t"
        "fma.rn.f32x2 %0, s, %3, %0;\n\t}"
        : "+l"(acc) : "l"(a), "l"(b), "l"(w));
}
__device__ __forceinline__ float lo32(ull a) {
    return __uint_as_float((unsigned int)(a & 0xffffffffull));
}
__device__ __forceinline__ float hi32(ull a) {
    return __uint_as_float((unsigned int)(a >> 32));
}
__device__ __forceinline__ float tanh_approx(float x) {
    float y;
    asm("tanh.approx.f32 %0, %1;" : "=f"(y) : "f"(x));
    return y;
}
__device__ __forceinline__ void cp16(unsigned int dst, const float* src) {
    asm volatile("cp.async.ca.shared.global [%0], [%1], 16;"
                 :: "r"(dst), "l"(src));
}

// ---------------------------------------------------------------------------
// Kernel A: projections — 512 threads/block for latency hiding.
// Grid (64, 2): x = 64-row tile, y = half (0 -> Wa/pre (+b1), 1 -> Wb/hj).
// 16 warps: warp w owns 4 cols (w-loads warp-broadcast, conflict-free);
// lane owns rows {lane, lane+32} (e-loads stride 130 -> conflict-free).
// Same per-block smem fill as the 256-thr version (no extra traffic), but
// 4 warps/SMSP instead of 2 -> double latency hiding.
// dyn smem = 2 * 64*130 * 4 = 66560 B
// ---------------------------------------------------------------------------
__global__ __launch_bounds__(512) void precompute_kernel(
    const float* __restrict__ emb, const float* __restrict__ W1,
    const float* __restrict__ b1)
{
    extern __shared__ float sh[];
    float* w1t = sh;              // 64 cols * 130
    float* es  = sh + 64 * 130;   // 64 rows * 130
    const int t = threadIdx.x;
    const int row0 = blockIdx.x * 64;
    const int half = blockIdx.y;  // 0 = Wa, 1 = Wb

    for (int idx = t; idx < 64 * 128; idx += 512) {
        int c = idx & 63, d = idx >> 6;
        w1t[c * 130 + d] = W1[(half * 128 + d) * 64 + c];
    }
    for (int idx = t; idx < 64 * 128; idx += 512) {
        int d = idx & 127, r = idx >> 7;
        es[r * 130 + d] = emb[(row0 + r) * 128 + d];
    }
    __syncthreads();

    const int lane = t & 31;
    const int w    = t >> 5;          // 0..15
    const int c0   = w * 4;           // 4 cols per warp

    ull acc[2][4];
    #pragma unroll
    for (int rr = 0; rr < 2; rr++)
        #pragma unroll
        for (int cc = 0; cc < 4; cc++)
            acc[rr][cc] = 0ull;

    const float* e0p = es + lane * 130;
    const float* e1p = es + (lane + 32) * 130;

    #pragma unroll 8
    for (int d = 0; d < 128; d += 2) {
        ull e0 = *(const ull*)(e0p + d);
        ull e1 = *(const ull*)(e1p + d);
        #pragma unroll
        for (int cc = 0; cc < 4; cc++) {
            ull wv = *(const ull*)(w1t + (c0 + cc) * 130 + d);
            fma2u(acc[0][cc], e0, wv);
            fma2u(acc[1][cc], e1, wv);
        }
    }

    float* dst = half ? g_hj : g_pre;
    #pragma unroll
    for (int rr = 0; rr < 2; rr++) {
        int rowg = row0 + lane + 32 * rr;
        float s[4];
        #pragma unroll
        for (int cc = 0; cc < 4; cc++) {
            s[cc] = lo32(acc[rr][cc]) + hi32(acc[rr][cc]);
            if (half == 0) s[cc] += b1[c0 + cc];
        }
        *(float4*)(dst + rowg * 64 + c0) = make_float4(s[0], s[1], s[2], s[3]);
    }
}

// ---------------------------------------------------------------------------
// Kernel B: fused pairwise core + tanh + symmetrize + negate.
// (R7 measured-best configuration, verbatim: 32.9 us.)
// Grid (136, 2): x = unordered tile pair (I <= J), y in {0,1}; each block
// does batches y and y+2 (single wave, 272 blocks); next-batch fill overlaps
// the epilogue.
// dyn smem = (4*64*68 + 64*65 + 64) * 4 = 86528 B -> 2 CTAs/SM
// ---------------------------------------------------------------------------
#define TSTRIDE 68
#define ARRW    (64 * TSTRIDE)       // 4352 words per array

__global__ __launch_bounds__(256, 2) void pair_sym_kernel(
    const float* __restrict__ W2, const float* __restrict__ b2,
    float* __restrict__ out)
{
    extern __shared__ float shB[];
    float* vs  = shB + 4 * ARRW;     // 64*65 transpose buffer
    float* w2s = vs + 64 * 65;       // 64

    const int t = threadIdx.x;

    // Decode unordered pair (I, J), I <= J
    int p = blockIdx.x;
    int I = 0;
    while (p >= 16 - I) { p -= 16 - I; I++; }
    const int J = I + p;

    // Fill: 64-thread group per array, 16 x 16B cp.async per thread.
    const int arr = t >> 6;          // 0..3
    const int sub = t & 63;
    const unsigned int sbase = (unsigned int)__cvta_generic_to_shared(shB);
    const unsigned int dbase = sbase + (unsigned int)(arr * ARRW) * 4u;

    auto fill_batch = [&](int b) {
        const int baseI = b * NSEQ + I * 64;
        const int baseJ = b * NSEQ + J * 64;
        const float* srcb =
            (arr == 0) ? g_pre + baseI * 64 :
            (arr == 1) ? g_hj  + baseI * 64 :
            (arr == 2) ? g_pre + baseJ * 64 :
                         g_hj  + baseJ * 64;
        #pragma unroll
        for (int e = 0; e < 16; e++) {
            int idx = sub + 64 * e;
            int row = idx >> 4;
            int q   = (idx & 15) * 4;
            cp16(dbase + (unsigned int)(row * TSTRIDE + q) * 4u,
                 srcb + row * 64 + q);
        }
        asm volatile("cp.async.commit_group;");
    };

    fill_batch(blockIdx.y);
    if (t < 64) w2s[t] = W2[t];

    const int tx = t & 15;
    const int ty = t >> 4;
    const float b2v = b2[0];

    const float* pAI = shB            + ty * TSTRIDE;   // preI rows
    const float* pHI = shB + ARRW     + ty * TSTRIDE;   // hjI rows
    const float* pPJ = shB + 2 * ARRW + tx * TSTRIDE;   // preJ rows
    const float* pHJ = shB + 3 * ARRW + tx * TSTRIDE;   // hjJ rows

    for (int bb = 0; bb < 2; bb++) {
        const int b = blockIdx.y + 2 * bb;

        ull acc1[4][4], acc2[4][4];
        #pragma unroll
        for (int r = 0; r < 4; r++)
            #pragma unroll
            for (int c = 0; c < 4; c++) { acc1[r][c] = 0ull; acc2[r][c] = 0ull; }

        asm volatile("cp.async.wait_group 0;");
        __syncthreads();

        #pragma unroll 2
        for (int hh = 0; hh < HDIM; hh += 4) {
            ulonglong2 wv = *(const ulonglong2*)(w2s + hh);
            ulonglong2 aI[4], bI[4];
            #pragma unroll
            for (int r = 0; r < 4; r++) {
                aI[r] = *(const ulonglong2*)(pAI + (16 * r) * TSTRIDE + hh);
                bI[r] = *(const ulonglong2*)(pHI + (16 * r) * TSTRIDE + hh);
            }
            #pragma unroll
            for (int c = 0; c < 4; c++) {
                ulonglong2 pJ = *(const ulonglong2*)(pPJ + (16 * c) * TSTRIDE + hh);
                ulonglong2 bJ = *(const ulonglong2*)(pHJ + (16 * c) * TSTRIDE + hh);
                #pragma unroll
                for (int r = 0; r < 4; r++) {
                    rfma(acc1[r][c], aI[r].x, bJ.x, wv.x);
                    rfma(acc1[r][c], aI[r].y, bJ.y, wv.y);
                    rfma(acc2[r][c], pJ.x, bI[r].x, wv.x);
                    rfma(acc2[r][c], pJ.y, bI[r].y, wv.y);
                }
            }
        }

        __syncthreads();                 // all warps done reading tiles
        if (bb == 0) fill_batch(blockIdx.y + 2);   // overlap with epilogue

        float* outB = out + (size_t)b * NSEQ * NSEQ;

        // Final values + direct (coalesced) store of out[I+i][J+j]
        float v[4][4];
        #pragma unroll
        for (int r = 0; r < 4; r++) {
            int i = ty + 16 * r;
            #pragma unroll
            for (int c = 0; c < 4; c++) {
                int j = tx + 16 * c;
                float s1 = lo32(acc1[r][c]) + hi32(acc1[r][c]) + b2v;
                float s2 = lo32(acc2[r][c]) + hi32(acc2[r][c]) + b2v;
                float vv = -0.5f * (tanh_approx(s1) + tanh_approx(s2));
                v[r][c] = vv;
                outB[(I * 64 + i) * NSEQ + (J * 64 + j)] = vv;
            }
        }

        // Mirror store out[J+j][I+i] via padded smem transpose (stride 65).
        #pragma unroll
        for (int r = 0; r < 4; r++)
            #pragma unroll
            for (int c = 0; c < 4; c++)
                vs[(ty + 16 * r) * 65 + (tx + 16 * c)] = v[r][c];
        __syncthreads();
        #pragma unroll
        for (int r = 0; r < 4; r++) {
            int jj = ty + 16 * r;
            #pragma unroll
            for (int c = 0; c < 4; c++) {
                int ii = tx + 16 * c;
                outB[(J * 64 + jj) * NSEQ + (I * 64 + ii)] = vs[ii * 65 + jj];
            }
        }
    }
}

// ---------------------------------------------------------------------------
extern "C" void kernel_launch(void* const* d_in, const int* in_sizes, int n_in,
                              void* d_out, int out_size)
{
    const float* emb = (const float*)d_in[0];
    const float* W1  = (const float*)d_in[1];
    const float* b1  = (const float*)d_in[2];
    const float* W2  = (const float*)d_in[3];
    const float* b2  = (const float*)d_in[4];
    float* out = (float*)d_out;

    const int smemA = 2 * 64 * 130 * 4;                    // 66560
    const int smemB = (4 * ARRW + 64 * 65 + 64) * 4;       // 86528

    cudaFuncSetAttribute(precompute_kernel,
                         cudaFuncAttributeMaxDynamicSharedMemorySize, smemA);
    cudaFuncSetAttribute(pair_sym_kernel,
                         cudaFuncAttributeMaxDynamicSharedMemorySize, smemB);

    precompute_kernel<<<dim3(64, 2), 512, smemA>>>(emb, W1, b1);
    pair_sym_kernel<<<dim3(136, 2), 256, smemB>>>(W2, b2, out);
}